// round 15
// baseline (speedup 1.0000x reference)
#include <cuda_runtime.h>
#include <math.h>

#define Bc  4
#define Lc  1024
#define Dc  512
#define Hc  8
#define Ec  4
#define Tc  (Bc*Lc)       // 4096 tokens

typedef unsigned long long u64;

__device__ __forceinline__ u64 pk2(float x, float y){ u64 r; asm("mov.b64 %0,{%1,%2};":"=l"(r):"f"(x),"f"(y)); return r; }
__device__ __forceinline__ float2 up2(u64 v){ float2 r; asm("mov.b64 {%0,%1},%2;":"=f"(r.x),"=f"(r.y):"l"(v)); return r; }
__device__ __forceinline__ u64 fma2v(u64 a,u64 b,u64 c){ u64 d; asm("fma.rn.f32x2 %0,%1,%2,%3;":"=l"(d):"l"(a),"l"(b),"l"(c)); return d; }
__device__ __forceinline__ u64 mul2v(u64 a,u64 b){ u64 d; asm("mul.rn.f32x2 %0,%1,%2;":"=l"(d):"l"(a),"l"(b)); return d; }

// ---------------- scratch ----------------
__device__ float g_q[Tc*Dc];
__device__ float g_k[Tc*Dc];
__device__ float g_v[Tc*Dc];
__device__ float g_gate[Tc*Dc];
__device__ float2 g_eb[Tc*Hc];
__device__ float g_w[Tc*Ec];
__device__ float g_o[(size_t)Ec*Tc*Hc*64];
__device__ float g_core[Tc*Dc];
__device__ int   g_list[Ec*Bc*Lc];
__device__ int   g_cnt[Ec*Bc];

// ---------------- multi-B GEMM (BM=128, BN=64, BK=16, double-buffered) ----------------
struct GemmBatch {
    const float* B[4];
    float*       C[4];
    int          act[4];
};

__global__ void __launch_bounds__(256) gemm_kernel(
        const float* __restrict__ A, GemmBatch gb, int K, int N) {
    __shared__ float As[2][16][132];
    __shared__ float Bs[2][16][64];
    int z = blockIdx.z;
    const float* __restrict__ B = gb.B[z];
    float* __restrict__ C = gb.C[z];
    int act = gb.act[z];

    int tid = threadIdx.x;
    int tx = tid & 15;
    int ty = tid >> 4;
    int m0 = blockIdx.y * 128;
    int n0 = blockIdx.x * 64;

    int mA = tid >> 2;
    int kA = (tid & 3) * 4;
    int kB = tid >> 4;
    int nB = (tid & 15) * 4;

    const float* Abase0 = A + (size_t)(m0 + mA)      * K + kA;
    const float* Abase1 = A + (size_t)(m0 + mA + 64) * K + kA;
    const float* Bbase  = B + (size_t)kB * N + n0 + nB;

    u64 acc2[4][4];
    #pragma unroll
    for (int i = 0; i < 4; i++)
        #pragma unroll
        for (int j = 0; j < 4; j++) acc2[i][j] = 0ull;

    int ntiles = K / 16;

    float4 a0 = *(const float4*)(Abase0);
    float4 a1 = *(const float4*)(Abase1);
    float4 b0 = *(const float4*)(Bbase);
    As[0][kA+0][mA] = a0.x; As[0][kA+1][mA] = a0.y;
    As[0][kA+2][mA] = a0.z; As[0][kA+3][mA] = a0.w;
    As[0][kA+0][mA+64] = a1.x; As[0][kA+1][mA+64] = a1.y;
    As[0][kA+2][mA+64] = a1.z; As[0][kA+3][mA+64] = a1.w;
    *(float4*)&Bs[0][kB][nB] = b0;
    __syncthreads();

    for (int it = 0; it < ntiles; it++) {
        int buf = it & 1;
        if (it + 1 < ntiles) {
            int kt = (it + 1) * 16;
            a0 = *(const float4*)(Abase0 + kt);
            a1 = *(const float4*)(Abase1 + kt);
            b0 = *(const float4*)(Bbase + (size_t)kt * N);
        }
        #pragma unroll
        for (int kk = 0; kk < 16; kk++) {
            u64 av[4];
            #pragma unroll
            for (int ri = 0; ri < 4; ri++)
                av[ri] = *(const u64*)&As[buf][kk][ty*8 + 2*ri];
            float4 bv = *(const float4*)&Bs[buf][kk][tx*4];
            u64 bb[4] = { pk2(bv.x,bv.x), pk2(bv.y,bv.y), pk2(bv.z,bv.z), pk2(bv.w,bv.w) };
            #pragma unroll
            for (int ri = 0; ri < 4; ri++)
                #pragma unroll
                for (int j = 0; j < 4; j++)
                    acc2[ri][j] = fma2v(av[ri], bb[j], acc2[ri][j]);
        }
        if (it + 1 < ntiles) {
            int nb = buf ^ 1;
            As[nb][kA+0][mA] = a0.x; As[nb][kA+1][mA] = a0.y;
            As[nb][kA+2][mA] = a0.z; As[nb][kA+3][mA] = a0.w;
            As[nb][kA+0][mA+64] = a1.x; As[nb][kA+1][mA+64] = a1.y;
            As[nb][kA+2][mA+64] = a1.z; As[nb][kA+3][mA+64] = a1.w;
            *(float4*)&Bs[nb][kB][nB] = b0;
        }
        __syncthreads();
    }

    #pragma unroll
    for (int ri = 0; ri < 4; ri++) {
        float r0[4], r1[4];
        #pragma unroll
        for (int j = 0; j < 4; j++) {
            float2 c = up2(acc2[ri][j]);
            r0[j] = c.x; r1[j] = c.y;
        }
        if (act >= 1) {
            #pragma unroll
            for (int j = 0; j < 4; j++) {
                r0[j] = r0[j] / (1.f + expf(-r0[j]));
                r1[j] = r1[j] / (1.f + expf(-r1[j]));
            }
        }
        if (act == 2) {
            float s0 = r0[0]*r0[0] + r0[1]*r0[1] + r0[2]*r0[2] + r0[3]*r0[3];
            float s1 = r1[0]*r1[0] + r1[1]*r1[1] + r1[2]*r1[2] + r1[3]*r1[3];
            #pragma unroll
            for (int off = 1; off < 16; off <<= 1) {
                s0 += __shfl_xor_sync(~0u, s0, off);
                s1 += __shfl_xor_sync(~0u, s1, off);
            }
            float n0f = rsqrtf(s0 + 1e-6f);
            float n1f = rsqrtf(s1 + 1e-6f);
            #pragma unroll
            for (int j = 0; j < 4; j++) { r0[j] *= n0f; r1[j] *= n1f; }
        }
        int m = m0 + ty*8 + 2*ri;
        *(float4*)&C[(size_t)m*N + n0 + tx*4]     = make_float4(r0[0],r0[1],r0[2],r0[3]);
        *(float4*)&C[(size_t)(m+1)*N + n0 + tx*4] = make_float4(r1[0],r1[1],r1[2],r1[3]);
    }
}

// ---------------- small projections ----------------
__global__ void smallproj_kernel(const float* __restrict__ h,
                                 const float* __restrict__ Wb,
                                 const float* __restrict__ Wa,
                                 const float* __restrict__ Wgate,
                                 const float* __restrict__ A_log,
                                 const float* __restrict__ dt_bias) {
    int warp = (blockIdx.x * blockDim.x + threadIdx.x) >> 5;
    int lane = threadIdx.x & 31;
    if (warp >= Tc) return;
    const float* hrow = h + (size_t)warp * Dc;

    float accB[Hc] = {}, accA[Hc] = {}, accG[Ec] = {};
    for (int i = 0; i < Dc/32; i++) {
        int r = i*32 + lane;
        float hv = hrow[r];
        #pragma unroll
        for (int c = 0; c < Hc; c++) {
            accB[c] = fmaf(hv, Wb[r*Hc + c], accB[c]);
            accA[c] = fmaf(hv, Wa[r*Hc + c], accA[c]);
        }
        #pragma unroll
        for (int c = 0; c < Ec; c++)
            accG[c] = fmaf(hv, Wgate[r*Ec + c], accG[c]);
    }
    #pragma unroll
    for (int c = 0; c < Hc; c++) {
        #pragma unroll
        for (int off = 16; off; off >>= 1) {
            accB[c] += __shfl_xor_sync(~0u, accB[c], off);
            accA[c] += __shfl_xor_sync(~0u, accA[c], off);
        }
    }
    #pragma unroll
    for (int c = 0; c < Ec; c++)
        #pragma unroll
        for (int off = 16; off; off >>= 1)
            accG[c] += __shfl_xor_sync(~0u, accG[c], off);

    if (lane < Hc) {
        int c = lane;
        float bet = 1.f / (1.f + expf(-accB[c]));
        float x = accA[c] + dt_bias[c];
        float sp = (x > 20.f) ? x : log1pf(expf(x));
        float eg = expf(-expf(A_log[c]) * sp);
        g_eb[warp*Hc + c] = make_float2(eg, bet);
    }
    if (lane == 0) {
        float m = fmaxf(fmaxf(accG[0], accG[1]), fmaxf(accG[2], accG[3]));
        float p[4]; float s = 0.f;
        #pragma unroll
        for (int e = 0; e < 4; e++) { p[e] = expf(accG[e] - m); s += p[e]; }
        #pragma unroll
        for (int e = 0; e < 4; e++) p[e] /= s;
        int i1 = 0;
        for (int e = 1; e < 4; e++) if (p[e] > p[i1]) i1 = e;
        int i2 = -1;
        for (int e = 0; e < 4; e++) { if (e == i1) continue; if (i2 < 0 || p[e] > p[i2]) i2 = e; }
        float den = p[i1] + p[i2];
        float w[4] = {0.f, 0.f, 0.f, 0.f};
        w[i1] = p[i1] / den;
        w[i2] = p[i2] / den;
        #pragma unroll
        for (int e = 0; e < 4; e++) g_w[warp*Ec + e] = w[e];
    }
}

// ---------------- compact routed-token lists ----------------
__global__ void __launch_bounds__(1024) compact_kernel() {
    int eb = blockIdx.x;
    int e = eb >> 2, b = eb & 3;
    int l = threadIdx.x;
    int warp = l >> 5, lane = l & 31;
    int t = b*Lc + l;
    bool on = g_w[t*Ec + e] > 0.f;
    unsigned mask = __ballot_sync(~0u, on);
    int pre = __popc(mask & ((1u << lane) - 1));
    __shared__ int wtot[32];
    if (lane == 31) wtot[warp] = pre + (on ? 1 : 0);
    __syncthreads();
    if (warp == 0) {
        int v = wtot[lane];
        #pragma unroll
        for (int off = 1; off < 32; off <<= 1) {
            int u = __shfl_up_sync(~0u, v, off);
            if (lane >= off) v += u;
        }
        wtot[lane] = v;
    }
    __syncthreads();
    int base = warp ? wtot[warp-1] : 0;
    if (on) g_list[eb*Lc + base + pre] = l;
    if (l == 1023) g_cnt[eb] = wtot[31];
}

// ---------------- scan: r=2 split, two heads per block (shared token list) ----------------
// block = (e,b,hpair); warps 0-3 -> h=2*hpair, warps 4-7 -> h=2*hpair+1.
// lane = j_local*2 + r; warp covers 16 columns; thread owns rows [32r,32r+32).
__global__ void __launch_bounds__(256, 1) scan_kernel() {
    int idx = blockIdx.x;            // e*16 + b*4 + hpair
    int e = idx >> 4;
    int b = (idx >> 2) & 3;
    int hpair = idx & 3;
    int tid  = threadIdx.x;
    int lane = tid & 31;
    int warp = tid >> 5;             // 0..7
    int half = warp >> 2;            // 0 or 1
    int wih  = warp & 3;             // warp in half
    int h = hpair*2 + half;
    int r = lane & 1;
    int j = wih * 16 + (lane >> 1);

    __shared__ int slist[Lc + 8];
    __shared__ __align__(16) float skq[2][2][8][160];   // [half][buf][tok][data]
    __shared__ __align__(16) float sv[2][2][8][64];
    __shared__ float2 seb[2][2][8];

    int ebi = e*Bc + b;
    int cnt = g_cnt[ebi];
    if (cnt == 0) return;
    const int* lst = &g_list[ebi*Lc];
    for (int i = tid; i < cnt; i += 256) slist[i] = b*Lc + lst[i];
    if (tid < 8) slist[cnt + tid] = b*Lc + lst[cnt - 1];
    __syncthreads();

    int ngroups = (cnt + 7) >> 3;

    int sc   = (lane < 16) ? lane : lane - 16;
    int soff = ((lane < 16) ? 0 : 80) + (sc >> 2) * 20 + (sc & 3) * 4;

    // stage group 0: each warp stages tokens wih and wih+4 for its half's head
    #pragma unroll
    for (int s = 0; s < 2; s++) {
        int m = wih + s*4;
        int t = slist[m];
        size_t base = ((size_t)t*Hc + h) * 64;
        float4 rkq = (lane < 16) ? *(const float4*)&g_k[base + sc*4]
                                 : *(const float4*)&g_q[base + sc*4];
        *(float4*)&skq[half][0][m][soff] = rkq;
        if (lane < 16) {
            float4 rv = *(const float4*)&g_v[base + sc*4];
            *(float4*)&sv[half][0][m][sc*4] = rv;
        }
        if (lane == 0) seb[half][0][m] = g_eb[t*Hc + h];
    }
    __syncthreads();

    u64 S2[16];
    #pragma unroll
    for (int p = 0; p < 16; p++) S2[p] = 0ull;

    for (int g = 0; g < ngroups; g++) {
        int buf = g & 1;
        bool more = (g + 1 < ngroups);

        // prefetch next group's two tokens for this warp
        float4 rkq0, rkq1, rv0, rv1; float2 reb0, reb1;
        if (more) {
            int gb8 = (g+1)*8;
            int t0 = slist[gb8 + wih];
            int t1 = slist[gb8 + wih + 4];
            size_t b0 = ((size_t)t0*Hc + h) * 64;
            size_t b1 = ((size_t)t1*Hc + h) * 64;
            rkq0 = (lane < 16) ? *(const float4*)&g_k[b0 + sc*4]
                               : *(const float4*)&g_q[b0 + sc*4];
            rkq1 = (lane < 16) ? *(const float4*)&g_k[b1 + sc*4]
                               : *(const float4*)&g_q[b1 + sc*4];
            if (lane < 16) {
                rv0 = *(const float4*)&g_v[b0 + sc*4];
                rv1 = *(const float4*)&g_v[b1 + sc*4];
            }
            if (lane == 0) {
                reb0 = g_eb[t0*Hc + h];
                reb1 = g_eb[t1*Hc + h];
            }
        }

        int tb = g * 8;
        #pragma unroll
        for (int m = 0; m < 8; m++) {
            if (tb + m < cnt) {
                const float* kp = &skq[half][buf][m][r*40];
                u64 k2[16];
                #pragma unroll
                for (int p = 0; p < 4; p++) {
                    ulonglong2 ka = *(const ulonglong2*)&kp[p*4];
                    ulonglong2 kb = *(const ulonglong2*)&kp[20 + p*4];
                    k2[2*p]   = ka.x; k2[2*p+1]   = ka.y;
                    k2[8+2*p] = kb.x; k2[8+2*p+1] = kb.y;
                }
                float2 ebv = seb[half][buf][m];
                float vj = sv[half][buf][m][j];
                u64 eg2 = pk2(ebv.x, ebv.x);

                u64 kvA = 0ull, kvB = 0ull, kvC = 0ull, kvD = 0ull;
                #pragma unroll
                for (int p = 0; p < 4; p++) {
                    S2[p]    = mul2v(S2[p],    eg2);
                    S2[p+4]  = mul2v(S2[p+4],  eg2);
                    S2[p+8]  = mul2v(S2[p+8],  eg2);
                    S2[p+12] = mul2v(S2[p+12], eg2);
                    kvA = fma2v(k2[p],    S2[p],    kvA);
                    kvB = fma2v(k2[p+4],  S2[p+4],  kvB);
                    kvC = fma2v(k2[p+8],  S2[p+8],  kvC);
                    kvD = fma2v(k2[p+12], S2[p+12], kvD);
                }
                float2 fa = up2(kvA), fb = up2(kvB), fc = up2(kvC), fd = up2(kvD);
                float kv = ((fa.x + fa.y) + (fb.x + fb.y)) + ((fc.x + fc.y) + (fd.x + fd.y));
                kv += __shfl_xor_sync(~0u, kv, 1);
                float delta = (vj - kv) * ebv.y;
                u64 d2 = pk2(delta, delta);

                // q unpacked EXACTLY like k: q2[i] pairs rows (2i,2i+1) => matches S2[i]
                const float* qp = kp + 80;
                u64 q2[16];
                #pragma unroll
                for (int p = 0; p < 4; p++) {
                    ulonglong2 qa = *(const ulonglong2*)&qp[p*4];
                    ulonglong2 qb = *(const ulonglong2*)&qp[20 + p*4];
                    q2[2*p]   = qa.x; q2[2*p+1]   = qa.y;
                    q2[8+2*p] = qb.x; q2[8+2*p+1] = qb.y;
                }
                u64 oA = 0ull, oB = 0ull, oC = 0ull, oD = 0ull;
                #pragma unroll
                for (int p = 0; p < 4; p++) {
                    S2[p]    = fma2v(k2[p],    d2, S2[p]);
                    S2[p+4]  = fma2v(k2[p+4],  d2, S2[p+4]);
                    S2[p+8]  = fma2v(k2[p+8],  d2, S2[p+8]);
                    S2[p+12] = fma2v(k2[p+12], d2, S2[p+12]);
                    oA = fma2v(q2[p],    S2[p],    oA);
                    oB = fma2v(q2[p+4],  S2[p+4],  oB);
                    oC = fma2v(q2[p+8],  S2[p+8],  oC);
                    oD = fma2v(q2[p+12], S2[p+12], oD);
                }
                float2 oa = up2(oA), ob = up2(oB), oc = up2(oC), od = up2(oD);
                float o = ((oa.x + oa.y) + (ob.x + ob.y)) + ((oc.x + oc.y) + (od.x + od.y));
                o += __shfl_xor_sync(~0u, o, 1);
                if (r == 0)
                    g_o[(((size_t)e*Tc + slist[tb+m])*Hc + h)*64 + j] = o * 0.125f;
            }
        }

        if (more) {
            int nb = buf ^ 1;
            *(float4*)&skq[half][nb][wih][soff]     = rkq0;
            *(float4*)&skq[half][nb][wih + 4][soff] = rkq1;
            if (lane < 16) {
                *(float4*)&sv[half][nb][wih][sc*4]     = rv0;
                *(float4*)&sv[half][nb][wih + 4][sc*4] = rv1;
            }
            if (lane == 0) {
                seb[half][nb][wih]     = reb0;
                seb[half][nb][wih + 4] = reb1;
            }
            __syncthreads();
        }
    }
}

// ---------------- combine experts + gated RMSNorm ----------------
__global__ void combine_kernel(const float* __restrict__ onw) {
    int t    = blockIdx.x;
    int h    = threadIdx.x >> 5;
    int lane = threadIdx.x & 31;

    float w[4];
    #pragma unroll
    for (int e = 0; e < 4; e++) w[e] = g_w[t*Ec + e];

    float c0 = 0.f, c1 = 0.f;
    #pragma unroll
    for (int e = 0; e < 4; e++) {
        if (w[e] > 0.f) {
            size_t base = (((size_t)e*Tc + t)*Hc + h) * 64;
            c0 = fmaf(w[e], g_o[base + lane],      c0);
            c1 = fmaf(w[e], g_o[base + lane + 32], c1);
        }
    }
    float ss = c0*c0 + c1*c1;
    #pragma unroll
    for (int off = 16; off; off >>= 1) ss += __shfl_xor_sync(~0u, ss, off);
    float r = rsqrtf(ss * (1.f/64.f) + 1e-5f);

    size_t gb = (size_t)t*Dc + h*64;
    float gt0 = g_gate[gb + lane];
    float gt1 = g_gate[gb + lane + 32];
    g_core[gb + lane]      = c0 * r * onw[lane]      * gt0;
    g_core[gb + lane + 32] = c1 * r * onw[lane + 32] * gt1;
}

// ---------------- launcher (1 stream, 3 events — proven-safe envelope) ----------------
extern "C" void kernel_launch(void* const* d_in, const int* in_sizes, int n_in,
                              void* d_out, int out_size) {
    const float* h     = (const float*)d_in[0];
    const float* Wq    = (const float*)d_in[1];
    const float* Wgate = (const float*)d_in[2];
    const float* Wk    = (const float*)d_in[3];
    const float* Wv    = (const float*)d_in[4];
    const float* Wb    = (const float*)d_in[5];
    const float* Wa    = (const float*)d_in[6];
    const float* A_log = (const float*)d_in[7];
    const float* dtb   = (const float*)d_in[8];
    const float* Wg    = (const float*)d_in[9];
    const float* onw   = (const float*)d_in[10];
    const float* Wo    = (const float*)d_in[11];
    float* out = (float*)d_out;

    float *pq, *pk, *pv, *pg, *pcore;
    cudaGetSymbolAddress((void**)&pq, g_q);
    cudaGetSymbolAddress((void**)&pk, g_k);
    cudaGetSymbolAddress((void**)&pv, g_v);
    cudaGetSymbolAddress((void**)&pg, g_gate);
    cudaGetSymbolAddress((void**)&pcore, g_core);

    static cudaStream_t s1 = nullptr;
    static cudaEvent_t evFork = nullptr, evJoin = nullptr, evGate = nullptr;
    if (s1 == nullptr) {
        cudaStreamCreateWithFlags(&s1, cudaStreamNonBlocking);
        cudaEventCreateWithFlags(&evFork, cudaEventDisableTiming);
        cudaEventCreateWithFlags(&evJoin, cudaEventDisableTiming);
        cudaEventCreateWithFlags(&evGate, cudaEventDisableTiming);
    }

    cudaEventRecord(evFork, 0);
    cudaStreamWaitEvent(s1, evFork, 0);

    GemmBatch gq;
    gq.B[0] = Wq; gq.C[0] = pq; gq.act[0] = 2;
    gq.B[1] = Wk; gq.C[1] = pk; gq.act[1] = 2;
    gq.B[2] = Wv; gq.C[2] = pv; gq.act[2] = 1;
    gq.B[3] = Wv; gq.C[3] = pv; gq.act[3] = 1;
    dim3 g3(Dc/64, Tc/128, 3);
    gemm_kernel<<<g3, 256>>>(h, gq, Dc, Dc);

    smallproj_kernel<<<Tc/8, 256, 0, s1>>>(h, Wb, Wa, Wgate, A_log, dtb);
    compact_kernel<<<Ec*Bc, 1024, 0, s1>>>();
    cudaEventRecord(evJoin, s1);
    GemmBatch gg;
    gg.B[0] = Wg; gg.C[0] = pg; gg.act[0] = 1;
    gg.B[1] = Wg; gg.C[1] = pg; gg.act[1] = 1;
    gg.B[2] = Wg; gg.C[2] = pg; gg.act[2] = 1;
    gg.B[3] = Wg; gg.C[3] = pg; gg.act[3] = 1;
    dim3 g1(Dc/64, Tc/128, 1);
    gemm_kernel<<<g1, 256, 0, s1>>>(h, gg, Dc, Dc);
    cudaEventRecord(evGate, s1);

    cudaStreamWaitEvent(0, evJoin, 0);
    scan_kernel<<<64, 256>>>();

    cudaStreamWaitEvent(0, evGate, 0);
    combine_kernel<<<Tc, 256>>>(onw);

    GemmBatch go;
    go.B[0] = Wo; go.C[0] = out; go.act[0] = 0;
    go.B[1] = Wo; go.C[1] = out; go.act[1] = 0;
    go.B[2] = Wo; go.C[2] = out; go.act[2] = 0;
    go.B[3] = Wo; go.C[3] = out; go.act[3] = 0;
    gemm_kernel<<<g1, 256>>>(pcore, go, Dc, Dc);
}

// round 16
// speedup vs baseline: 1.0927x; 1.0927x over previous
#include <cuda_runtime.h>
#include <math.h>

#define Bc  4
#define Lc  1024
#define Dc  512
#define Hc  8
#define Ec  4
#define Tc  (Bc*Lc)       // 4096 tokens

typedef unsigned long long u64;

__device__ __forceinline__ u64 pk2(float x, float y){ u64 r; asm("mov.b64 %0,{%1,%2};":"=l"(r):"f"(x),"f"(y)); return r; }
__device__ __forceinline__ float2 up2(u64 v){ float2 r; asm("mov.b64 {%0,%1},%2;":"=f"(r.x),"=f"(r.y):"l"(v)); return r; }
__device__ __forceinline__ u64 fma2v(u64 a,u64 b,u64 c){ u64 d; asm("fma.rn.f32x2 %0,%1,%2,%3;":"=l"(d):"l"(a),"l"(b),"l"(c)); return d; }
__device__ __forceinline__ u64 mul2v(u64 a,u64 b){ u64 d; asm("mul.rn.f32x2 %0,%1,%2;":"=l"(d):"l"(a),"l"(b)); return d; }

// ---------------- scratch ----------------
__device__ float g_q[Tc*Dc];
__device__ float g_k[Tc*Dc];
__device__ float g_v[Tc*Dc];
__device__ float g_gate[Tc*Dc];
__device__ float2 g_eb[Tc*Hc];
__device__ float g_w[Tc*Ec];
__device__ float g_o[(size_t)Ec*Tc*Hc*64];
__device__ float g_core[Tc*Dc];
__device__ int   g_list[Ec*Bc*Lc];
__device__ int   g_cnt[Ec*Bc];

// ---------------- multi-B GEMM (BM=128, BN=64, BK=16, double-buffered) ----------------
struct GemmBatch {
    const float* B[4];
    float*       C[4];
    int          act[4];
};

__global__ void __launch_bounds__(256) gemm_kernel(
        const float* __restrict__ A, GemmBatch gb, int K, int N) {
    __shared__ float As[2][16][132];
    __shared__ float Bs[2][16][64];
    int z = blockIdx.z;
    const float* __restrict__ B = gb.B[z];
    float* __restrict__ C = gb.C[z];
    int act = gb.act[z];

    int tid = threadIdx.x;
    int tx = tid & 15;
    int ty = tid >> 4;
    int m0 = blockIdx.y * 128;
    int n0 = blockIdx.x * 64;

    int mA = tid >> 2;
    int kA = (tid & 3) * 4;
    int kB = tid >> 4;
    int nB = (tid & 15) * 4;

    const float* Abase0 = A + (size_t)(m0 + mA)      * K + kA;
    const float* Abase1 = A + (size_t)(m0 + mA + 64) * K + kA;
    const float* Bbase  = B + (size_t)kB * N + n0 + nB;

    u64 acc2[4][4];
    #pragma unroll
    for (int i = 0; i < 4; i++)
        #pragma unroll
        for (int j = 0; j < 4; j++) acc2[i][j] = 0ull;

    int ntiles = K / 16;

    float4 a0 = *(const float4*)(Abase0);
    float4 a1 = *(const float4*)(Abase1);
    float4 b0 = *(const float4*)(Bbase);
    As[0][kA+0][mA] = a0.x; As[0][kA+1][mA] = a0.y;
    As[0][kA+2][mA] = a0.z; As[0][kA+3][mA] = a0.w;
    As[0][kA+0][mA+64] = a1.x; As[0][kA+1][mA+64] = a1.y;
    As[0][kA+2][mA+64] = a1.z; As[0][kA+3][mA+64] = a1.w;
    *(float4*)&Bs[0][kB][nB] = b0;
    __syncthreads();

    for (int it = 0; it < ntiles; it++) {
        int buf = it & 1;
        if (it + 1 < ntiles) {
            int kt = (it + 1) * 16;
            a0 = *(const float4*)(Abase0 + kt);
            a1 = *(const float4*)(Abase1 + kt);
            b0 = *(const float4*)(Bbase + (size_t)kt * N);
        }
        #pragma unroll
        for (int kk = 0; kk < 16; kk++) {
            u64 av[4];
            #pragma unroll
            for (int ri = 0; ri < 4; ri++)
                av[ri] = *(const u64*)&As[buf][kk][ty*8 + 2*ri];
            float4 bv = *(const float4*)&Bs[buf][kk][tx*4];
            u64 bb[4] = { pk2(bv.x,bv.x), pk2(bv.y,bv.y), pk2(bv.z,bv.z), pk2(bv.w,bv.w) };
            #pragma unroll
            for (int ri = 0; ri < 4; ri++)
                #pragma unroll
                for (int j = 0; j < 4; j++)
                    acc2[ri][j] = fma2v(av[ri], bb[j], acc2[ri][j]);
        }
        if (it + 1 < ntiles) {
            int nb = buf ^ 1;
            As[nb][kA+0][mA] = a0.x; As[nb][kA+1][mA] = a0.y;
            As[nb][kA+2][mA] = a0.z; As[nb][kA+3][mA] = a0.w;
            As[nb][kA+0][mA+64] = a1.x; As[nb][kA+1][mA+64] = a1.y;
            As[nb][kA+2][mA+64] = a1.z; As[nb][kA+3][mA+64] = a1.w;
            *(float4*)&Bs[nb][kB][nB] = b0;
        }
        __syncthreads();
    }

    #pragma unroll
    for (int ri = 0; ri < 4; ri++) {
        float r0[4], r1[4];
        #pragma unroll
        for (int j = 0; j < 4; j++) {
            float2 c = up2(acc2[ri][j]);
            r0[j] = c.x; r1[j] = c.y;
        }
        if (act >= 1) {
            #pragma unroll
            for (int j = 0; j < 4; j++) {
                r0[j] = r0[j] / (1.f + expf(-r0[j]));
                r1[j] = r1[j] / (1.f + expf(-r1[j]));
            }
        }
        if (act == 2) {
            float s0 = r0[0]*r0[0] + r0[1]*r0[1] + r0[2]*r0[2] + r0[3]*r0[3];
            float s1 = r1[0]*r1[0] + r1[1]*r1[1] + r1[2]*r1[2] + r1[3]*r1[3];
            #pragma unroll
            for (int off = 1; off < 16; off <<= 1) {
                s0 += __shfl_xor_sync(~0u, s0, off);
                s1 += __shfl_xor_sync(~0u, s1, off);
            }
            float n0f = rsqrtf(s0 + 1e-6f);
            float n1f = rsqrtf(s1 + 1e-6f);
            #pragma unroll
            for (int j = 0; j < 4; j++) { r0[j] *= n0f; r1[j] *= n1f; }
        }
        int m = m0 + ty*8 + 2*ri;
        *(float4*)&C[(size_t)m*N + n0 + tx*4]     = make_float4(r0[0],r0[1],r0[2],r0[3]);
        *(float4*)&C[(size_t)(m+1)*N + n0 + tx*4] = make_float4(r1[0],r1[1],r1[2],r1[3]);
    }
}

// ---------------- small projections ----------------
__global__ void smallproj_kernel(const float* __restrict__ h,
                                 const float* __restrict__ Wb,
                                 const float* __restrict__ Wa,
                                 const float* __restrict__ Wgate,
                                 const float* __restrict__ A_log,
                                 const float* __restrict__ dt_bias) {
    int warp = (blockIdx.x * blockDim.x + threadIdx.x) >> 5;
    int lane = threadIdx.x & 31;
    if (warp >= Tc) return;
    const float* hrow = h + (size_t)warp * Dc;

    float accB[Hc] = {}, accA[Hc] = {}, accG[Ec] = {};
    for (int i = 0; i < Dc/32; i++) {
        int r = i*32 + lane;
        float hv = hrow[r];
        #pragma unroll
        for (int c = 0; c < Hc; c++) {
            accB[c] = fmaf(hv, Wb[r*Hc + c], accB[c]);
            accA[c] = fmaf(hv, Wa[r*Hc + c], accA[c]);
        }
        #pragma unroll
        for (int c = 0; c < Ec; c++)
            accG[c] = fmaf(hv, Wgate[r*Ec + c], accG[c]);
    }
    #pragma unroll
    for (int c = 0; c < Hc; c++) {
        #pragma unroll
        for (int off = 16; off; off >>= 1) {
            accB[c] += __shfl_xor_sync(~0u, accB[c], off);
            accA[c] += __shfl_xor_sync(~0u, accA[c], off);
        }
    }
    #pragma unroll
    for (int c = 0; c < Ec; c++)
        #pragma unroll
        for (int off = 16; off; off >>= 1)
            accG[c] += __shfl_xor_sync(~0u, accG[c], off);

    if (lane < Hc) {
        int c = lane;
        float bet = 1.f / (1.f + expf(-accB[c]));
        float x = accA[c] + dt_bias[c];
        float sp = (x > 20.f) ? x : log1pf(expf(x));
        float eg = expf(-expf(A_log[c]) * sp);
        g_eb[warp*Hc + c] = make_float2(eg, bet);
    }
    if (lane == 0) {
        float m = fmaxf(fmaxf(accG[0], accG[1]), fmaxf(accG[2], accG[3]));
        float p[4]; float s = 0.f;
        #pragma unroll
        for (int e = 0; e < 4; e++) { p[e] = expf(accG[e] - m); s += p[e]; }
        #pragma unroll
        for (int e = 0; e < 4; e++) p[e] /= s;
        int i1 = 0;
        for (int e = 1; e < 4; e++) if (p[e] > p[i1]) i1 = e;
        int i2 = -1;
        for (int e = 0; e < 4; e++) { if (e == i1) continue; if (i2 < 0 || p[e] > p[i2]) i2 = e; }
        float den = p[i1] + p[i2];
        float w[4] = {0.f, 0.f, 0.f, 0.f};
        w[i1] = p[i1] / den;
        w[i2] = p[i2] / den;
        #pragma unroll
        for (int e = 0; e < 4; e++) g_w[warp*Ec + e] = w[e];
    }
}

// ---------------- compact routed-token lists ----------------
__global__ void __launch_bounds__(1024) compact_kernel() {
    int eb = blockIdx.x;
    int e = eb >> 2, b = eb & 3;
    int l = threadIdx.x;
    int warp = l >> 5, lane = l & 31;
    int t = b*Lc + l;
    bool on = g_w[t*Ec + e] > 0.f;
    unsigned mask = __ballot_sync(~0u, on);
    int pre = __popc(mask & ((1u << lane) - 1));
    __shared__ int wtot[32];
    if (lane == 31) wtot[warp] = pre + (on ? 1 : 0);
    __syncthreads();
    if (warp == 0) {
        int v = wtot[lane];
        #pragma unroll
        for (int off = 1; off < 32; off <<= 1) {
            int u = __shfl_up_sync(~0u, v, off);
            if (lane >= off) v += u;
        }
        wtot[lane] = v;
    }
    __syncthreads();
    int base = warp ? wtot[warp-1] : 0;
    if (on) g_list[eb*Lc + base + pre] = l;
    if (l == 1023) g_cnt[eb] = wtot[31];
}

// ---------------- smem-staged scan: 16-token groups; q loaded at use (R13 config) ----------------
struct Tok {
    u64    k2[8];
    float  v;
    float2 eb;
    int    t;
};

__global__ void __launch_bounds__(256, 1) scan_kernel() {
    int idx = blockIdx.x;            // e*32 + b*8 + h
    int e = idx >> 5;
    int b = (idx >> 3) & 3;
    int h = idx & 7;
    int tid  = threadIdx.x;
    int lane = tid & 31;
    int warp = tid >> 5;
    int r  = lane & 3;
    int j  = warp * 8 + (lane >> 2);

    __shared__ int slist[Lc + 32];
    __shared__ __align__(16) float skq[2][16][160];
    __shared__ __align__(16) float sv[2][16][64];
    __shared__ float2 seb[2][16];

    int ebi = e*Bc + b;
    int cnt = g_cnt[ebi];
    if (cnt == 0) return;
    const int* lst = &g_list[ebi*Lc];
    for (int i = tid; i < cnt; i += 256) slist[i] = b*Lc + lst[i];
    if (tid < 32) slist[cnt + tid] = b*Lc + lst[cnt - 1];
    __syncthreads();

    int ngroups = (cnt + 15) >> 4;

    int sc   = (lane < 16) ? lane : lane - 16;
    int soff = ((lane < 16) ? 0 : 80) + (sc >> 2) * 20 + (sc & 3) * 4;

    // hoisted output base: g_o[((e*Tc + t)*Hc + h)*64 + j] = obase + t*(Hc*64)
    float* obase = g_o + ((size_t)e*Tc*Hc + h) * 64 + j;

    #pragma unroll
    for (int s = 0; s < 2; s++) {
        int m = warp + s*8;
        int t = slist[m];
        size_t base = ((size_t)t*Hc + h) * 64;
        float4 rkq = (lane < 16) ? *(const float4*)&g_k[base + sc*4]
                                 : *(const float4*)&g_q[base + sc*4];
        *(float4*)&skq[0][m][soff] = rkq;
        if (lane < 16) {
            float4 rv = *(const float4*)&g_v[base + sc*4];
            *(float4*)&sv[0][m][sc*4] = rv;
        }
        if (lane == 0) seb[0][m] = g_eb[t*Hc + h];
    }
    __syncthreads();

    u64 S2[8];
    #pragma unroll
    for (int p = 0; p < 8; p++) S2[p] = 0ull;

    for (int g = 0; g < ngroups; g++) {
        int buf = g & 1;
        bool more = (g + 1 < ngroups);

        float4 rkq0, rkq1, rv0, rv1; float2 reb0, reb1;
        if (more) {
            int gb16 = (g+1)*16;
            int t0 = slist[gb16 + warp];
            int t1 = slist[gb16 + warp + 8];
            size_t b0 = ((size_t)t0*Hc + h) * 64;
            size_t b1 = ((size_t)t1*Hc + h) * 64;
            rkq0 = (lane < 16) ? *(const float4*)&g_k[b0 + sc*4]
                               : *(const float4*)&g_q[b0 + sc*4];
            rkq1 = (lane < 16) ? *(const float4*)&g_k[b1 + sc*4]
                               : *(const float4*)&g_q[b1 + sc*4];
            if (lane < 16) {
                rv0 = *(const float4*)&g_v[b0 + sc*4];
                rv1 = *(const float4*)&g_v[b1 + sc*4];
            }
            if (lane == 0) {
                reb0 = g_eb[t0*Hc + h];
                reb1 = g_eb[t1*Hc + h];
            }
        }

        int tb = g * 16;
        const float* kqb = &skq[buf][0][0];
        const float* svb = &sv[buf][0][0];
        const float2* ebb = &seb[buf][0];

        Tok A, B;
        #define LDS_TOK(T, m)  do {                                              \
            const float* kp = kqb + (m)*160 + r*20;                              \
            _Pragma("unroll")                                                    \
            for (int p = 0; p < 4; p++) {                                        \
                ulonglong2 kk = *(const ulonglong2*)&kp[p*4];                    \
                (T).k2[2*p] = kk.x; (T).k2[2*p+1] = kk.y;                        \
            }                                                                    \
            (T).v  = svb[(m)*64 + j];                                            \
            (T).eb = ebb[m];                                                     \
            (T).t  = slist[tb + (m)];                                            \
        } while(0)

        #define TOK_STEP(T, m)  do {                                             \
            const float* qp = kqb + (m)*160 + 80 + r*20;                         \
            u64 q2[8];                                                           \
            _Pragma("unroll")                                                    \
            for (int p = 0; p < 4; p++) {                                        \
                ulonglong2 qq = *(const ulonglong2*)&qp[p*4];                    \
                q2[2*p] = qq.x; q2[2*p+1] = qq.y;                                \
            }                                                                    \
            u64 eg2 = pk2((T).eb.x, (T).eb.x);                                   \
            u64 kvA = 0ull, kvB = 0ull;                                          \
            _Pragma("unroll")                                                    \
            for (int p = 0; p < 4; p++) {                                        \
                S2[p]   = mul2v(S2[p],   eg2);                                   \
                S2[p+4] = mul2v(S2[p+4], eg2);                                   \
                kvA = fma2v((T).k2[p],   S2[p],   kvA);                          \
                kvB = fma2v((T).k2[p+4], S2[p+4], kvB);                          \
            }                                                                    \
            float2 ka = up2(kvA), kb = up2(kvB);                                 \
            float kv = (ka.x + ka.y) + (kb.x + kb.y);                            \
            float x1 = __shfl_xor_sync(~0u, kv, 1);                              \
            float x2 = __shfl_xor_sync(~0u, kv, 2);                              \
            float x3 = __shfl_xor_sync(~0u, kv, 3);                              \
            kv = (kv + x1) + (x2 + x3);                                          \
            float delta = ((T).v - kv) * (T).eb.y;                               \
            u64 d2 = pk2(delta, delta);                                          \
            u64 oA = 0ull, oB = 0ull;                                            \
            _Pragma("unroll")                                                    \
            for (int p = 0; p < 4; p++) {                                        \
                S2[p]   = fma2v((T).k2[p],   d2, S2[p]);                         \
                S2[p+4] = fma2v((T).k2[p+4], d2, S2[p+4]);                       \
                oA = fma2v(q2[p],   S2[p],   oA);                                \
                oB = fma2v(q2[p+4], S2[p+4], oB);                                \
            }                                                                    \
            float2 oa = up2(oA), ob = up2(oB);                                   \
            float o = (oa.x + oa.y) + (ob.x + ob.y);                             \
            float y1 = __shfl_xor_sync(~0u, o, 1);                               \
            float y2 = __shfl_xor_sync(~0u, o, 2);                               \
            float y3 = __shfl_xor_sync(~0u, o, 3);                               \
            o = (o + y1) + (y2 + y3);                                            \
            if (r == 0)                                                          \
                obase[(size_t)(T).t * (Hc*64)] = o * 0.125f;                     \
        } while(0)

        LDS_TOK(A, 0);
        LDS_TOK(B, 1);
        #pragma unroll
        for (int m = 0; m < 14; m++) {
            if ((m & 1) == 0) {
                if (tb + m < cnt) TOK_STEP(A, m);
                LDS_TOK(A, m + 2);
            } else {
                if (tb + m < cnt) TOK_STEP(B, m);
                LDS_TOK(B, m + 2);
            }
        }
        if (tb + 14 < cnt) TOK_STEP(A, 14);
        if (tb + 15 < cnt) TOK_STEP(B, 15);

        #undef LDS_TOK
        #undef TOK_STEP

        if (more) {
            int nb = buf ^ 1;
            *(float4*)&skq[nb][warp][soff]     = rkq0;
            *(float4*)&skq[nb][warp + 8][soff] = rkq1;
            if (lane < 16) {
                *(float4*)&sv[nb][warp][sc*4]     = rv0;
                *(float4*)&sv[nb][warp + 8][sc*4] = rv1;
            }
            if (lane == 0) {
                seb[nb][warp]     = reb0;
                seb[nb][warp + 8] = reb1;
            }
            __syncthreads();
        }
    }
}

// ---------------- combine experts + gated RMSNorm ----------------
__global__ void combine_kernel(const float* __restrict__ onw) {
    int t    = blockIdx.x;
    int h    = threadIdx.x >> 5;
    int lane = threadIdx.x & 31;

    float w[4];
    #pragma unroll
    for (int e = 0; e < 4; e++) w[e] = g_w[t*Ec + e];

    float c0 = 0.f, c1 = 0.f;
    #pragma unroll
    for (int e = 0; e < 4; e++) {
        if (w[e] > 0.f) {
            size_t base = (((size_t)e*Tc + t)*Hc + h) * 64;
            c0 = fmaf(w[e], g_o[base + lane],      c0);
            c1 = fmaf(w[e], g_o[base + lane + 32], c1);
        }
    }
    float ss = c0*c0 + c1*c1;
    #pragma unroll
    for (int off = 16; off; off >>= 1) ss += __shfl_xor_sync(~0u, ss, off);
    float r = rsqrtf(ss * (1.f/64.f) + 1e-5f);

    size_t gb = (size_t)t*Dc + h*64;
    float gt0 = g_gate[gb + lane];
    float gt1 = g_gate[gb + lane + 32];
    g_core[gb + lane]      = c0 * r * onw[lane]      * gt0;
    g_core[gb + lane + 32] = c1 * r * onw[lane + 32] * gt1;
}

// ---------------- launcher (1 stream, 3 events — proven-safe envelope) ----------------
extern "C" void kernel_launch(void* const* d_in, const int* in_sizes, int n_in,
                              void* d_out, int out_size) {
    const float* h     = (const float*)d_in[0];
    const float* Wq    = (const float*)d_in[1];
    const float* Wgate = (const float*)d_in[2];
    const float* Wk    = (const float*)d_in[3];
    const float* Wv    = (const float*)d_in[4];
    const float* Wb    = (const float*)d_in[5];
    const float* Wa    = (const float*)d_in[6];
    const float* A_log = (const float*)d_in[7];
    const float* dtb   = (const float*)d_in[8];
    const float* Wg    = (const float*)d_in[9];
    const float* onw   = (const float*)d_in[10];
    const float* Wo    = (const float*)d_in[11];
    float* out = (float*)d_out;

    float *pq, *pk, *pv, *pg, *pcore;
    cudaGetSymbolAddress((void**)&pq, g_q);
    cudaGetSymbolAddress((void**)&pk, g_k);
    cudaGetSymbolAddress((void**)&pv, g_v);
    cudaGetSymbolAddress((void**)&pg, g_gate);
    cudaGetSymbolAddress((void**)&pcore, g_core);

    static cudaStream_t s1 = nullptr;
    static cudaEvent_t evFork = nullptr, evJoin = nullptr, evGate = nullptr;
    if (s1 == nullptr) {
        cudaStreamCreateWithFlags(&s1, cudaStreamNonBlocking);
        cudaEventCreateWithFlags(&evFork, cudaEventDisableTiming);
        cudaEventCreateWithFlags(&evJoin, cudaEventDisableTiming);
        cudaEventCreateWithFlags(&evGate, cudaEventDisableTiming);
    }

    cudaEventRecord(evFork, 0);
    cudaStreamWaitEvent(s1, evFork, 0);

    GemmBatch gq;
    gq.B[0] = Wq; gq.C[0] = pq; gq.act[0] = 2;
    gq.B[1] = Wk; gq.C[1] = pk; gq.act[1] = 2;
    gq.B[2] = Wv; gq.C[2] = pv; gq.act[2] = 1;
    gq.B[3] = Wv; gq.C[3] = pv; gq.act[3] = 1;
    dim3 g3(Dc/64, Tc/128, 3);
    gemm_kernel<<<g3, 256>>>(h, gq, Dc, Dc);

    smallproj_kernel<<<Tc/8, 256, 0, s1>>>(h, Wb, Wa, Wgate, A_log, dtb);
    compact_kernel<<<Ec*Bc, 1024, 0, s1>>>();
    cudaEventRecord(evJoin, s1);
    GemmBatch gg;
    gg.B[0] = Wg; gg.C[0] = pg; gg.act[0] = 1;
    gg.B[1] = Wg; gg.C[1] = pg; gg.act[1] = 1;
    gg.B[2] = Wg; gg.C[2] = pg; gg.act[2] = 1;
    gg.B[3] = Wg; gg.C[3] = pg; gg.act[3] = 1;
    dim3 g1(Dc/64, Tc/128, 1);
    gemm_kernel<<<g1, 256, 0, s1>>>(h, gg, Dc, Dc);
    cudaEventRecord(evGate, s1);

    cudaStreamWaitEvent(0, evJoin, 0);
    scan_kernel<<<128, 256>>>();

    cudaStreamWaitEvent(0, evGate, 0);
    combine_kernel<<<Tc, 256>>>(onw);

    GemmBatch go;
    go.B[0] = Wo; go.C[0] = out; go.act[0] = 0;
    go.B[1] = Wo; go.C[1] = out; go.act[1] = 0;
    go.B[2] = Wo; go.C[2] = out; go.act[2] = 0;
    go.B[3] = Wo; go.C[3] = out; go.act[3] = 0;
    gemm_kernel<<<g1, 256>>>(pcore, go, Dc, Dc);
}